// round 7
// baseline (speedup 1.0000x reference)
#include <cuda_runtime.h>

#define W 224
#define WW (W * W)                  // 50176
#define F4_PER (WW / 4)             // 12544 float4 per sample
#define F4_PER_ROW (W / 4)          // 56
#define NSAMP 256
#define BLK_PER_SAMP 2
#define NBLK (NSAMP * BLK_PER_SAMP)   // 512  (< 4 CTA/SM * 148 SM = 592 resident)
#define F4_HALF (F4_PER / BLK_PER_SAMP)  // 6272 f4 per block
#define LN2 0.6931471805599453

// Scratch (device globals; zero-init at load; reset by last block each call)
__device__ int4     g_blk[NBLK];    // per-block {maxbits, cnt, si, sj}
__device__ unsigned g_sync;         // phase-1 arrive counter
__device__ unsigned g_cnt;          // finalize ticket
__device__ double   g_acc;

__device__ __forceinline__ float fast_lg2(float x) {
    float r; asm("lg2.approx.f32 %0, %1;" : "=f"(r) : "f"(x)); return r;
}
__device__ __forceinline__ float fast_sqrt(float x) {
    float r; asm("sqrt.approx.f32 %0, %1;" : "=f"(r) : "f"(x)); return r;
}
__device__ __forceinline__ float fast_rcp(float x) {
    float r; asm("rcp.approx.f32 %0, %1;" : "=f"(r) : "f"(x)); return r;
}

// ---------------------------------------------------------------------------
// Fused kernel: 512 blocks (2 per sample, guaranteed co-resident).
//   Phase A: block max over its 100KB target slice (DRAM -> L1)
//   Phase B: tie stats, re-reading the slice (L1-hot)
//   grid barrier (atomic arrive + spin)
//   Phase C: weighted BCE over the same slice (target L1-hot, input DRAM)
//   last block: write out[0], reset counters (graph-replay safe)
// ---------------------------------------------------------------------------
__global__ __launch_bounds__(256, 4)
void k_fused(const float* __restrict__ inp, const float* __restrict__ tgt,
             float* __restrict__ out, double scale) {
    const int bid  = blockIdx.x;
    const int samp = bid >> 1;
    const int half = bid & 1;
    const int tid  = threadIdx.x;
    const int wid = tid >> 5, lid = tid & 31;

    const size_t base = (size_t)samp * F4_PER + half * F4_HALF;
    const float4* __restrict__ t4 = reinterpret_cast<const float4*>(tgt) + base;
    const float4* __restrict__ p4 = reinterpret_cast<const float4*>(inp) + base;

    __shared__ float smax[8];
    __shared__ float sM;
    __shared__ int   scnt, ssi, ssj;
    __shared__ float2 sxy;
    __shared__ float sw[8];

    // ---- Phase A: block max (branch-free, unrolled for MLP) ----
    float m0 = -3.0e38f, m1 = m0;
    #pragma unroll 4
    for (int p = tid; p < F4_HALF; p += 256) {
        float4 v = t4[p];
        m0 = fmaxf(m0, fmaxf(v.x, v.y));
        m1 = fmaxf(m1, fmaxf(v.z, v.w));
    }
    float m = fmaxf(m0, m1);
    #pragma unroll
    for (int o = 16; o > 0; o >>= 1)
        m = fmaxf(m, __shfl_xor_sync(0xffffffffu, m, o));
    if (lid == 0) smax[wid] = m;
    if (tid == 0) { scnt = 0; ssi = 0; ssj = 0; }
    __syncthreads();
    if (tid == 0) {
        float bm = smax[0];
        #pragma unroll
        for (int w = 1; w < 8; w++) bm = fmaxf(bm, smax[w]);
        sM = bm;
    }
    __syncthreads();
    const float M = sM;

    // ---- Phase B: tie stats, re-read slice (L1-hot) ----
    {
        int cnt = 0, si = 0, sj = 0;
        #pragma unroll 4
        for (int p = tid; p < F4_HALF; p += 256) {
            float4 v = t4[p];
            float mm = fmaxf(fmaxf(v.x, v.y), fmaxf(v.z, v.w));
            if (mm == M) {                 // extremely rare
                const int r4 = half * F4_HALF + p;
                const int i  = r4 / F4_PER_ROW;
                const int j0 = (r4 - i * F4_PER_ROW) * 4;
                if (v.x == M) { cnt++; si += i; sj += j0;     }
                if (v.y == M) { cnt++; si += i; sj += j0 + 1; }
                if (v.z == M) { cnt++; si += i; sj += j0 + 2; }
                if (v.w == M) { cnt++; si += i; sj += j0 + 3; }
            }
        }
        if (cnt) {
            atomicAdd_block(&scnt, cnt);
            atomicAdd_block(&ssi,  si);
            atomicAdd_block(&ssj,  sj);
        }
    }
    __syncthreads();

    // ---- publish stats + grid barrier ----
    if (tid == 0) {
        g_blk[bid] = make_int4((int)__float_as_uint(M), scnt, ssi, ssj);
        __threadfence();
        atomicAdd(&g_sync, 1u);
        while (atomicAdd(&g_sync, 0u) < NBLK) __nanosleep(128);
        __threadfence();
        // combine the two halves of this sample
        int4 e0 = g_blk[samp * 2];
        int4 e1 = g_blk[samp * 2 + 1];
        unsigned mb = max((unsigned)e0.x, (unsigned)e1.x);
        int cnt = 0, si = 0, sj = 0;
        if ((unsigned)e0.x == mb) { cnt += e0.y; si += e0.z; sj += e0.w; }
        if ((unsigned)e1.x == mb) { cnt += e1.y; si += e1.z; sj += e1.w; }
        const float inv = 1.0f / (float)cnt;
        sxy = make_float2((float)si * inv, (float)sj * inv);
    }
    __syncthreads();
    const float cx = sxy.x, cy = sxy.y;

    // ---- Phase C: weighted BCE (target L1-hot, input DRAM) ----
    float s = 0.0f;
    #pragma unroll 4
    for (int p = tid; p < F4_HALF; p += 256) {
        float4 pv = p4[p];
        float4 tv = t4[p];

        const int r4 = half * F4_HALF + p;
        const int i  = r4 / F4_PER_ROW;
        const int j0 = (r4 - i * F4_PER_ROW) * 4;
        const float di  = (float)i - cx;
        const float di2 = di * di;
        const float dj0 = (float)j0 - cy;

        float pe[4] = {pv.x, pv.y, pv.z, pv.w};
        float te[4] = {tv.x, tv.y, tv.z, tv.w};
        #pragma unroll
        for (int e = 0; e < 4; e++) {
            float dj  = dj0 + (float)e;
            float d2  = fmaf(dj, dj, di2);
            float wr  = fast_rcp(fast_sqrt(d2) + 1.0f);     // 1/(sqrt(d2)+1)
            float lp2 = fast_lg2(pe[e]);                    // log2 p
            float lq2 = fast_lg2(1.0f - pe[e]);             // log2 (1-p)
            float bce = fmaf(te[e], lq2 - lp2, -lq2);       // -(t lp + (1-t) lq), log2 units
            s = fmaf(wr, bce, s);
        }
    }

    #pragma unroll
    for (int o = 16; o > 0; o >>= 1)
        s += __shfl_xor_sync(0xffffffffu, s, o);
    if (lid == 0) sw[wid] = s;
    __syncthreads();
    if (tid == 0) {
        float bs = sw[0];
        #pragma unroll
        for (int w = 1; w < 8; w++) bs += sw[w];
        atomicAdd(&g_acc, (double)bs);
        __threadfence();
        const unsigned ticket = atomicAdd(&g_cnt, 1u);
        if (ticket == NBLK - 1) {           // last block: finalize + reset all
            const double total = atomicAdd(&g_acc, 0.0);
            out[0] = (float)(total * scale);
            g_acc  = 0.0;
            g_cnt  = 0u;
            g_sync = 0u;
        }
    }
}

extern "C" void kernel_launch(void* const* d_in, const int* in_sizes, int n_in,
                              void* d_out, int out_size) {
    const float* inp = (const float*)d_in[0];
    const float* tgt = (const float*)d_in[1];
    float* out = (float*)d_out;

    // scale = W * ln2 / N  (W: weight numerator; ln2: log2->ln; 1/N: mean)
    const double scale = (double)W * LN2 / (double)((size_t)NSAMP * WW);
    k_fused<<<NBLK, 256>>>(inp, tgt, out, scale);
}

// round 11
// speedup vs baseline: 1.7369x; 1.7369x over previous
#include <cuda_runtime.h>

#define W 224
#define WW (W * W)                  // 50176
#define F4_PER (WW / 4)             // 12544 float4 per sample
#define F4_PER_ROW (W / 4)          // 56
#define NSAMP 256
#define BLK_PER_SAMP 7
#define NBLK1 (NSAMP * BLK_PER_SAMP)        // 1792
#define F4_PER_BLK (F4_PER / BLK_PER_SAMP)  // 1792 f4 = 32 rows per chunk
#define NBLK2 NBLK1
#define LOSS_THREADS 224                    // = 4 rows of 56 f4
#define LOSS_ITERS (F4_PER_BLK / LOSS_THREADS)  // 8
#define LN2 0.6931471805599453

// Scratch (device globals; zero-init at load; g_acc/g_cnt reset by last block)
__device__ int4     g_blk[NBLK1];   // per-block {maxbits, cnt, si, sj}
__device__ double   g_acc;
__device__ unsigned g_cnt;

__device__ __forceinline__ float fast_lg2(float x) {
    float r; asm("lg2.approx.f32 %0, %1;" : "=f"(r) : "f"(x)); return r;
}
__device__ __forceinline__ float fast_sqrt(float x) {
    float r; asm("sqrt.approx.f32 %0, %1;" : "=f"(r) : "f"(x)); return r;
}
__device__ __forceinline__ float fast_rcp(float x) {
    float r; asm("rcp.approx.f32 %0, %1;" : "=f"(r) : "f"(x)); return r;
}

// ---------------------------------------------------------------------------
// Kernel 1: per-block max + tie stats in ONE pass (ties counted from registers).
// grid = 1792 (7 blocks/sample), 256 threads, 7 float4 per thread. (R6, proven)
// ---------------------------------------------------------------------------
__global__ __launch_bounds__(256) void k_maxstats(const float* __restrict__ tgt) {
    const int b = blockIdx.x / BLK_PER_SAMP;
    const int c = blockIdx.x - b * BLK_PER_SAMP;
    const int tid = threadIdx.x;
    const float4* __restrict__ t4 =
        reinterpret_cast<const float4*>(tgt) + (size_t)b * F4_PER + c * F4_PER_BLK;

    float4 v[7];
    #pragma unroll
    for (int k = 0; k < 7; k++) v[k] = t4[k * 256 + tid];

    float tmax = -3.0e38f;
    #pragma unroll
    for (int k = 0; k < 7; k++)
        tmax = fmaxf(tmax, fmaxf(fmaxf(v[k].x, v[k].y), fmaxf(v[k].z, v[k].w)));

    float m = tmax;
    #pragma unroll
    for (int o = 16; o > 0; o >>= 1)
        m = fmaxf(m, __shfl_xor_sync(0xffffffffu, m, o));

    __shared__ float smax[8];
    __shared__ float sM;
    __shared__ int scnt, ssi, ssj;
    const int wid = tid >> 5, lid = tid & 31;
    if (lid == 0) smax[wid] = m;
    if (tid == 0) { scnt = 0; ssi = 0; ssj = 0; }
    __syncthreads();
    if (tid == 0) {
        float bm = smax[0];
        #pragma unroll
        for (int w = 1; w < 8; w++) bm = fmaxf(bm, smax[w]);
        sM = bm;
    }
    __syncthreads();
    const float M = sM;

    if (tmax == M) {   // rare: only threads holding the block max
        int cnt = 0, si = 0, sj = 0;
        #pragma unroll
        for (int k = 0; k < 7; k++) {
            const int r4 = c * F4_PER_BLK + k * 256 + tid;
            const int i  = r4 / F4_PER_ROW;
            const int j0 = (r4 - i * F4_PER_ROW) * 4;
            if (v[k].x == M) { cnt++; si += i; sj += j0;     }
            if (v[k].y == M) { cnt++; si += i; sj += j0 + 1; }
            if (v[k].z == M) { cnt++; si += i; sj += j0 + 2; }
            if (v[k].w == M) { cnt++; si += i; sj += j0 + 3; }
        }
        atomicAdd_block(&scnt, cnt);
        atomicAdd_block(&ssi,  si);
        atomicAdd_block(&ssj,  sj);
    }
    __syncthreads();

    if (tid == 0) {
        const unsigned mb = __float_as_uint(M);   // target >= 0 -> bit order == float order
        g_blk[blockIdx.x] = make_int4((int)mb, scnt, ssi, ssj);
    }
}

// ---------------------------------------------------------------------------
// Kernel 2: weighted BCE, row-aligned indexing. grid = (7, 256), 224 threads.
// Chunk c = 32 rows; thread handles col4 = tid%56 in rows (c*32 + k*4 + tid/56).
// All index math hoisted out of the element loop; no divides in hot path.
// ---------------------------------------------------------------------------
__global__ __launch_bounds__(LOSS_THREADS) void k_loss(const float* __restrict__ inp,
                                                       const float* __restrict__ tgt,
                                                       float* __restrict__ out,
                                                       double scale) {
    const int samp = blockIdx.y;
    const int c    = blockIdx.x;
    const int tid  = threadIdx.x;

    __shared__ float2 sxy;
    if (tid == 0) {
        int4 e[BLK_PER_SAMP];
        #pragma unroll
        for (int q = 0; q < BLK_PER_SAMP; q++) e[q] = g_blk[samp * BLK_PER_SAMP + q];
        unsigned mb = 0u;
        #pragma unroll
        for (int q = 0; q < BLK_PER_SAMP; q++) mb = max(mb, (unsigned)e[q].x);
        int cnt = 0, si = 0, sj = 0;
        #pragma unroll
        for (int q = 0; q < BLK_PER_SAMP; q++)
            if ((unsigned)e[q].x == mb) { cnt += e[q].y; si += e[q].z; sj += e[q].w; }
        const float inv = 1.0f / (float)cnt;
        sxy = make_float2((float)si * inv, (float)sj * inv);
    }
    __syncthreads();
    const float cx = sxy.x, cy = sxy.y;

    // one-time index decomposition
    const int rq = tid / F4_PER_ROW;            // row offset within 4-row group
    const int cq = tid - rq * F4_PER_ROW;       // f4 column (0..55)
    const float di_base = (float)(c * 32 + rq) - cx;   // row dist for k=0
    const float dj0     = (float)(cq * 4) - cy;        // col dist for lane e=0

    const size_t base = (size_t)samp * F4_PER + c * F4_PER_BLK;
    const float4* __restrict__ p4 = reinterpret_cast<const float4*>(inp) + base;
    const float4* __restrict__ t4 = reinterpret_cast<const float4*>(tgt) + base;

    float s = 0.0f;

    // software pipeline: loads for k+1 in flight while processing k
    float4 pv = p4[tid];
    float4 tv = t4[tid];
    #pragma unroll
    for (int k = 0; k < LOSS_ITERS; k++) {
        float4 pn, tn;
        if (k < LOSS_ITERS - 1) {
            pn = p4[(k + 1) * LOSS_THREADS + tid];
            tn = t4[(k + 1) * LOSS_THREADS + tid];
        }

        const float di  = di_base + (float)(4 * k);   // folded per unrolled k
        const float di2 = di * di;

        float pe[4] = {pv.x, pv.y, pv.z, pv.w};
        float te[4] = {tv.x, tv.y, tv.z, tv.w};
        #pragma unroll
        for (int e = 0; e < 4; e++) {
            float dj  = dj0 + (float)e;
            float d2  = fmaf(dj, dj, di2);
            float wr  = fast_rcp(fast_sqrt(d2) + 1.0f);   // 1/(sqrt(d2)+1)
            float lp2 = fast_lg2(pe[e]);                  // log2 p
            float lq2 = fast_lg2(1.0f - pe[e]);           // log2 (1-p)
            float bce = fmaf(te[e], lq2 - lp2, -lq2);     // -(t lp + (1-t) lq), log2 units
            s = fmaf(wr, bce, s);
        }
        pv = pn; tv = tn;
    }

    #pragma unroll
    for (int o = 16; o > 0; o >>= 1)
        s += __shfl_xor_sync(0xffffffffu, s, o);

    __shared__ float sw[7];
    const int wid = tid >> 5, lid = tid & 31;
    if (lid == 0) sw[wid] = s;
    __syncthreads();
    if (tid == 0) {
        float bs = sw[0];
        #pragma unroll
        for (int w = 1; w < 7; w++) bs += sw[w];
        atomicAdd(&g_acc, (double)bs);
        __threadfence();
        const unsigned ticket = atomicAdd(&g_cnt, 1u);
        if (ticket == NBLK2 - 1) {          // last block: finalize + reset
            const double total = atomicAdd(&g_acc, 0.0);
            out[0] = (float)(total * scale);
            g_acc = 0.0;
            g_cnt = 0u;
        }
    }
}

extern "C" void kernel_launch(void* const* d_in, const int* in_sizes, int n_in,
                              void* d_out, int out_size) {
    const float* inp = (const float*)d_in[0];
    const float* tgt = (const float*)d_in[1];
    float* out = (float*)d_out;

    k_maxstats<<<NBLK1, 256>>>(tgt);
    dim3 g2(BLK_PER_SAMP, NSAMP);
    // scale = W * ln2 / N  (W: weight numerator; ln2: log2->ln; 1/N: mean)
    const double scale = (double)W * LN2 / (double)((size_t)NSAMP * WW);
    k_loss<<<g2, LOSS_THREADS>>>(inp, tgt, out, scale);
}